// round 13
// baseline (speedup 1.0000x reference)
#include <cuda_runtime.h>
#include <cuda_fp16.h>
#include <math.h>
#include <stdint.h>

#define BB 32
#define CC 512
#define NN 1024      // H*W = 32*32
#define HEADS 8
#define HD 64
#define BN_EPS 1e-5f
#define BCN ((size_t)BB * CC * NN)

// ---------------- scratch (device globals; no allocation allowed) ----------------
__device__ __half g_QKVh[3 * BCN];                // Q,K,V half
__device__ __half g_Gh[BCN];                      // dwconv output half
__device__ __half g_Oh[BCN];                      // attention output half
__device__ __half g_Xh[BCN];                      // x in half
__device__ __half g_Wh[3 * (size_t)CC * CC];      // Wq,Wk,Wv stacked half
__device__ __half g_Wph[(size_t)CC * CC];         // Wp half
__device__ __half g_attnh[(size_t)BB * HEADS * HD * HD];
__device__ float  g_bnsum[CC];
__device__ float  g_bnsum2[CC];
__device__ float  g_bnA[CC];
__device__ float  g_bnB[CC];

// ============================ helpers ============================
__device__ __forceinline__ uint32_t smem_u32(const void* p) {
    uint32_t a;
    asm("{ .reg .u64 t; cvta.to.shared.u64 t, %1; cvt.u32.u64 %0, t; }" : "=r"(a) : "l"(p));
    return a;
}
__device__ __forceinline__ void cp_async16(uint32_t dst, const void* src) {
    asm volatile("cp.async.cg.shared.global [%0], [%1], 16;" :: "r"(dst), "l"(src));
}
#define CP_COMMIT() asm volatile("cp.async.commit_group;" ::: "memory")
#define CP_WAIT(n)  asm volatile("cp.async.wait_group %0;" :: "n"(n) : "memory")

__device__ __forceinline__ void ldsm4(uint32_t* r, uint32_t addr) {
    asm volatile("ldmatrix.sync.aligned.m8n8.x4.shared.b16 {%0,%1,%2,%3}, [%4];"
        : "=r"(r[0]), "=r"(r[1]), "=r"(r[2]), "=r"(r[3]) : "r"(addr));
}
__device__ __forceinline__ void ldsm4t(uint32_t* r, uint32_t addr) {
    asm volatile("ldmatrix.sync.aligned.m8n8.x4.trans.shared.b16 {%0,%1,%2,%3}, [%4];"
        : "=r"(r[0]), "=r"(r[1]), "=r"(r[2]), "=r"(r[3]) : "r"(addr));
}
__device__ __forceinline__ void mma_f16(float* c, const uint32_t* a, const uint32_t* b) {
    asm volatile("mma.sync.aligned.m16n8k16.row.col.f32.f16.f16.f32 "
        "{%0,%1,%2,%3}, {%4,%5,%6,%7}, {%8,%9}, {%0,%1,%2,%3};"
        : "+f"(c[0]), "+f"(c[1]), "+f"(c[2]), "+f"(c[3])
        : "r"(a[0]), "r"(a[1]), "r"(a[2]), "r"(a[3]), "r"(b[0]), "r"(b[1]));
}

// ============================ small kernels ============================
__global__ void zero_bn_kernel() {
    int t = threadIdx.x;
    if (t < CC) { g_bnsum[t] = 0.f; g_bnsum2[t] = 0.f; }
}

__global__ void bn_finalize_kernel(const float* __restrict__ gamma,
                                   const float* __restrict__ beta) {
    int c = threadIdx.x;
    if (c < CC) {
        const float cnt = (float)(BB * NN);
        float mean = g_bnsum[c] / cnt;
        float var  = g_bnsum2[c] / cnt - mean * mean;
        float A = gamma[c] * rsqrtf(var + BN_EPS);
        g_bnA[c] = A;
        g_bnB[c] = beta[c] - mean * A;
    }
}

__global__ __launch_bounds__(256)
void f2h_kernel(const float* __restrict__ in, __half* __restrict__ out, int n4) {
    int i = blockIdx.x * 256 + threadIdx.x;
    if (i < n4) {
        float4 v = ((const float4*)in)[i];
        __half2* o = (__half2*)out;
        o[2 * i]     = __floats2half2_rn(v.x, v.y);
        o[2 * i + 1] = __floats2half2_rn(v.z, v.w);
    }
}

__global__ __launch_bounds__(256)
void f2h_w_kernel(const float* __restrict__ wq, const float* __restrict__ wk,
                  const float* __restrict__ wv, const float* __restrict__ wp,
                  __half* __restrict__ wh, __half* __restrict__ wph)
{
    const int n4 = CC * CC / 4;
    int i = blockIdx.x * 256 + threadIdx.x;
    int m = i / n4, r = i - m * n4;
    const float* src = (m == 0) ? wq : (m == 1) ? wk : (m == 2) ? wv : wp;
    __half* dst = (m < 3) ? (wh + (size_t)m * CC * CC) : wph;
    float4 v = ((const float4*)src)[r];
    __half2* o = (__half2*)dst;
    o[2 * r]     = __floats2half2_rn(v.x, v.y);
    o[2 * r + 1] = __floats2half2_rn(v.z, v.w);
}

// ---- fp16 tensor GEMM: CTA tile 256x128, warp tile 64x64, 4-stage cp.async ----
#define ASTRH 40
#define BSTRH 136
#define STAGES 4
#define TM 256
#define A_STAGE_BYTES (TM * ASTRH * 2)            // 20480
#define B_STAGE_BYTES (32 * BSTRH * 2)            // 8704
#define STAGE_BYTES (A_STAGE_BYTES + B_STAGE_BYTES)   // 29184
#define GEMM_SMEM (STAGES * STAGE_BYTES)          // 116736

template <typename OT>
__global__ __launch_bounds__(256, 1)
void gemm_h(const __half* __restrict__ A, const __half* __restrict__ Bh,
            OT* __restrict__ Y, const float* __restrict__ bias)
{
    extern __shared__ __half dsm[];
    const uint32_t base = smem_u32(dsm);

    const int t    = threadIdx.x;
    const int lane = t & 31;
    const int wid  = t >> 5;
    const int wm   = wid & 3;                      // 4 warps over M (64 rows each)
    const int wn   = wid >> 2;                     // 2 warps over N (64 cols each)
    const int m0g  = blockIdx.y * TM;
    const int mat  = m0g >> 9;
    const int mrow0 = m0g & 511;
    const int n0   = blockIdx.x * 128;
    const int b    = blockIdx.z;

    const __half* Ag = A + (size_t)m0g * CC;
    const __half* Bg = Bh + (size_t)b * CC * NN + n0;
    OT*           Yb = Y + (size_t)mat * BCN + (size_t)b * CC * NN;

    float acc[4][8][4];
    #pragma unroll
    for (int i = 0; i < 4; i++)
        #pragma unroll
        for (int j = 0; j < 8; j++)
            #pragma unroll
            for (int q = 0; q < 4; q++) acc[i][j][q] = 0.f;

    auto ld_stage = [&](int s, int k0) {
        const uint32_t au = base + (uint32_t)s * STAGE_BYTES;
        const uint32_t bu = au + A_STAGE_BYTES;
        #pragma unroll
        for (int i = 0; i < 4; i++) {              // A: 256x32 halves
            int idx = t + 256 * i;
            int r = idx >> 2, j = idx & 3;
            cp_async16(au + (uint32_t)(r * ASTRH + j * 8) * 2u,
                       Ag + (size_t)r * CC + k0 + j * 8);
        }
        #pragma unroll
        for (int i = 0; i < 2; i++) {              // B: 32x128 halves
            int idx = t + 256 * i;
            int r = idx >> 4, j = idx & 15;
            cp_async16(bu + (uint32_t)(r * BSTRH + j * 8) * 2u,
                       Bg + (size_t)(k0 + r) * NN + j * 8);
        }
    };

    #pragma unroll
    for (int s = 0; s < STAGES - 1; s++) { ld_stage(s, s * 32); CP_COMMIT(); }

    const int gid = lane >> 2, tig = lane & 3;
    const int arow = lane & 15, achk = lane >> 4;

    for (int c = 0; c < 16; c++) {
        CP_WAIT(STAGES - 2);
        __syncthreads();

        const uint32_t Au = base + (uint32_t)(c & (STAGES - 1)) * STAGE_BYTES;
        const uint32_t Bu = Au + A_STAGE_BYTES;

        #pragma unroll
        for (int ks = 0; ks < 2; ks++) {
            uint32_t ra[4][4];
            #pragma unroll
            for (int mi = 0; mi < 4; mi++) {
                int row = wm * 64 + mi * 16 + arow;
                ldsm4(ra[mi], Au + (uint32_t)(row * ASTRH + ks * 16 + achk * 8) * 2u);
            }
            uint32_t rb[4][4];
            #pragma unroll
            for (int nb = 0; nb < 4; nb++) {
                int krow = ks * 16 + arow;
                int col  = wn * 64 + nb * 16 + achk * 8;
                ldsm4t(rb[nb], Bu + (uint32_t)(krow * BSTRH + col) * 2u);
            }
            #pragma unroll
            for (int mi = 0; mi < 4; mi++)
                #pragma unroll
                for (int j = 0; j < 8; j++)
                    mma_f16(acc[mi][j], ra[mi], &rb[j >> 1][(j & 1) * 2]);
        }

        if (c + STAGES - 1 < 16) ld_stage((c + STAGES - 1) & (STAGES - 1),
                                          (c + STAGES - 1) * 32);
        CP_COMMIT();
    }

    #pragma unroll
    for (int mi = 0; mi < 4; mi++) {
        int ml = mrow0 + wm * 64 + mi * 16 + gid;
        float b0 = bias ? bias[ml] : 0.f;
        float b1 = bias ? bias[ml + 8] : 0.f;
        OT* r0 = Yb + (size_t)ml * NN + n0 + wn * 64;
        OT* r1 = r0 + 8 * NN;
        #pragma unroll
        for (int j = 0; j < 8; j++) {
            int cb = j * 8 + 2 * tig;
            if constexpr (sizeof(OT) == 4) {
                *(float2*)((float*)r0 + cb) = make_float2(acc[mi][j][0] + b0, acc[mi][j][1] + b0);
                *(float2*)((float*)r1 + cb) = make_float2(acc[mi][j][2] + b1, acc[mi][j][3] + b1);
            } else {
                *(__half2*)((__half*)r0 + cb) = __floats2half2_rn(acc[mi][j][0] + b0, acc[mi][j][1] + b0);
                *(__half2*)((__half*)r1 + cb) = __floats2half2_rn(acc[mi][j][2] + b1, acc[mi][j][3] + b1);
            }
        }
    }
}

// ---- attn = softmax( (Q K^T)/(|q||k|) * temp ) per (b,h), tensor-core gram, half out ----
#define QSTR 72
__global__ __launch_bounds__(128)
void attn_kernel(const __half* __restrict__ Q, const __half* __restrict__ K,
                 const float* __restrict__ temp, __half* __restrict__ attn)
{
    const int bh = blockIdx.x;
    const int b = bh / HEADS, h = bh % HEADS;
    const __half* Qb = Q + (size_t)b * CC * NN + (size_t)h * HD * NN;
    const __half* Kb = K + (size_t)b * CC * NN + (size_t)h * HD * NN;

    __shared__ __half Qs[64 * QSTR];
    __shared__ __half Ks[64 * QSTR];
    __shared__ float Ss[64 * 65];
    __shared__ float ssq[64], ssk[64], inv_q[64], inv_k[64];

    const int t = threadIdx.x;
    const int lane = t & 31;
    const int wid = t >> 5;
    const int wm = wid >> 1, wn = wid & 1;

    if (t < 64) { ssq[t] = 0.f; ssk[t] = 0.f; }
    __syncthreads();

    const uint32_t QsU = smem_u32(Qs), KsU = smem_u32(Ks);

    float acc[2][4][4];
    #pragma unroll
    for (int mi = 0; mi < 2; mi++)
        #pragma unroll
        for (int j = 0; j < 4; j++)
            #pragma unroll
            for (int q = 0; q < 4; q++) acc[mi][j][q] = 0.f;

    float accq4[4] = {0.f, 0.f, 0.f, 0.f};
    float acck4[4] = {0.f, 0.f, 0.f, 0.f};

    for (int ch = 0; ch < 16; ch++) {
        const int n0 = ch * 64;
        #pragma unroll
        for (int i = 0; i < 4; i++) {
            int c = t + 128 * i;
            int r = c >> 3, j = c & 7;
            uint4 v = *(const uint4*)(Qb + (size_t)r * NN + n0 + j * 8);
            *(uint4*)&Qs[r * QSTR + j * 8] = v;
            const __half2* hp = (const __half2*)&v;
            #pragma unroll
            for (int q = 0; q < 4; q++) { float2 f = __half22float2(hp[q]); accq4[i] += f.x * f.x + f.y * f.y; }
            uint4 w = *(const uint4*)(Kb + (size_t)r * NN + n0 + j * 8);
            *(uint4*)&Ks[r * QSTR + j * 8] = w;
            const __half2* hq = (const __half2*)&w;
            #pragma unroll
            for (int q = 0; q < 4; q++) { float2 f = __half22float2(hq[q]); acck4[i] += f.x * f.x + f.y * f.y; }
        }
        __syncthreads();

        #pragma unroll
        for (int ks = 0; ks < 4; ks++) {
            uint32_t ra[2][4], rb[2][4];
            #pragma unroll
            for (int mi = 0; mi < 2; mi++)
                ldsm4(ra[mi], QsU + (uint32_t)((wm * 32 + mi * 16 + (lane & 15)) * QSTR
                                               + ks * 16 + (lane >> 4) * 8) * 2u);
            #pragma unroll
            for (int nb = 0; nb < 2; nb++)
                ldsm4(rb[nb], KsU + (uint32_t)((wn * 32 + nb * 16 + (lane & 15)) * QSTR
                                               + ks * 16 + (lane >> 4) * 8) * 2u);
            #pragma unroll
            for (int mi = 0; mi < 2; mi++)
                #pragma unroll
                for (int j = 0; j < 4; j++) {
                    uint32_t bb[2] = { rb[j >> 1][j & 1], rb[j >> 1][(j & 1) + 2] };
                    mma_f16(acc[mi][j], ra[mi], bb);
                }
        }
        __syncthreads();
    }

    #pragma unroll
    for (int i = 0; i < 4; i++) {
        int r = (t + 128 * i) >> 3;
        atomicAdd(&ssq[r], accq4[i]);
        atomicAdd(&ssk[r], acck4[i]);
    }
    __syncthreads();

    if (t < 64) {
        inv_q[t] = 1.f / fmaxf(sqrtf(ssq[t]), 1e-12f);
        inv_k[t] = 1.f / fmaxf(sqrtf(ssk[t]), 1e-12f);
    }
    __syncthreads();

    const float tmp = temp[h];
    const int gid = lane >> 2, tig = lane & 3;
    #pragma unroll
    for (int mi = 0; mi < 2; mi++)
        #pragma unroll
        for (int j = 0; j < 4; j++)
            #pragma unroll
            for (int q = 0; q < 4; q++) {
                int m = wm * 32 + mi * 16 + gid + ((q >> 1) << 3);
                int n = wn * 32 + j * 8 + 2 * tig + (q & 1);
                Ss[m * 65 + n] = acc[mi][j][q] * inv_q[m] * inv_k[n] * tmp;
            }
    __syncthreads();

    if (t < 64) {
        float mx = -1e30f;
        #pragma unroll 8
        for (int e = 0; e < 64; e++) mx = fmaxf(mx, Ss[t * 65 + e]);
        float sum = 0.f;
        #pragma unroll 8
        for (int e = 0; e < 64; e++) {
            float ev = __expf(Ss[t * 65 + e] - mx);
            Ss[t * 65 + e] = ev; sum += ev;
        }
        float inv = 1.f / sum;
        __half* out = attn + ((size_t)bh * HD + t) * HD;
        #pragma unroll 8
        for (int e = 0; e < 64; e += 2)
            *(__half2*)(out + e) = __floats2half2_rn(Ss[t * 65 + e] * inv,
                                                     Ss[t * 65 + e + 1] * inv);
    }
}

// ---------------- depthwise 3x3 conv (half out) + per-channel stats ----------------
__global__ __launch_bounds__(256)
void dwconv_kernel(const float* __restrict__ x, const float* __restrict__ dw,
                   __half* __restrict__ g)
{
    const int bc = blockIdx.x;
    const int c = bc % CC;
    const float* img = x + (size_t)bc * NN;

    __shared__ float sm[34][34];
    const int t = threadIdx.x;
    for (int i = t; i < 34 * 34; i += 256) {
        int yy = i / 34 - 1, xx = i % 34 - 1;
        sm[i / 34][i % 34] =
            (yy >= 0 && yy < 32 && xx >= 0 && xx < 32) ? img[yy * 32 + xx] : 0.f;
    }
    float w[9];
    #pragma unroll
    for (int i = 0; i < 9; i++) w[i] = dw[c * 9 + i];
    __syncthreads();

    float s = 0.f, s2 = 0.f;
    for (int p = t; p < NN; p += 256) {
        int y = p >> 5, xx = p & 31;
        float acc = 0.f;
        #pragma unroll
        for (int dy = 0; dy < 3; dy++)
            #pragma unroll
            for (int dx = 0; dx < 3; dx++)
                acc += sm[y + dy][xx + dx] * w[dy * 3 + dx];
        g[(size_t)bc * NN + p] = __float2half_rn(acc);
        s += acc; s2 += acc * acc;
    }

    __shared__ float r1[256], r2[256];
    r1[t] = s; r2[t] = s2; __syncthreads();
    for (int st = 128; st > 0; st >>= 1) {
        if (t < st) { r1[t] += r1[t + st]; r2[t] += r2[t + st]; }
        __syncthreads();
    }
    if (t == 0) { atomicAdd(&g_bnsum[c], r1[0]); atomicAdd(&g_bnsum2[c], r2[0]); }
}

// ---- tensorized: O[b,h](64 x 128chunk) = attn(64x64,half) @ (V*silu(bn(G)))(64x128) ----
#define VSTR 136
__global__ __launch_bounds__(128)
void attn_apply_kernel(const __half* __restrict__ attn, const __half* __restrict__ v,
                       const __half* __restrict__ gbuf, __half* __restrict__ o)
{
    const int bh = blockIdx.x;
    const int nc = blockIdx.y;
    const int b = bh / HEADS, h = bh % HEADS;
    const __half* A  = attn + (size_t)bh * HD * HD;
    const __half* Vb = v    + (size_t)b * CC * NN + (size_t)h * HD * NN + nc * 128;
    const __half* Gb = gbuf + (size_t)b * CC * NN + (size_t)h * HD * NN + nc * 128;
    __half*       Ob = o    + (size_t)b * CC * NN + (size_t)h * HD * NN + nc * 128;

    __shared__ __half Ah[64 * QSTR];
    __shared__ __half Bsm[64 * VSTR];
    __shared__ float sc[64], sh[64];

    const int t = threadIdx.x;
    const int lane = t & 31;
    const int w = t >> 5;

    if (t < 64) {
        sc[t] = g_bnA[h * 64 + t];
        sh[t] = g_bnB[h * 64 + t];
    }
    #pragma unroll
    for (int i = 0; i < 4; i++) {
        int cidx = t + 128 * i;
        int r = cidx >> 3, j = cidx & 7;
        *(uint4*)&Ah[r * QSTR + j * 8] = *(const uint4*)(A + r * 64 + j * 8);
    }
    __syncthreads();

    #pragma unroll
    for (int i = 0; i < 8; i++) {
        int cidx = t + 128 * i;
        int r = cidx >> 4, j = cidx & 15;
        uint4 vv = *(const uint4*)(Vb + (size_t)r * NN + j * 8);
        uint4 gg = *(const uint4*)(Gb + (size_t)r * NN + j * 8);
        const float Ac = sc[r], Bc = sh[r];
        __half2 res[4];
        const __half2* vp = (const __half2*)&vv;
        const __half2* gp = (const __half2*)&gg;
        #pragma unroll
        for (int q = 0; q < 4; q++) {
            float2 gf = __half22float2(gp[q]);
            float2 vf = __half22float2(vp[q]);
            float gn0 = gf.x * Ac + Bc, gn1 = gf.y * Ac + Bc;
            float gt0 = gn0 / (1.f + __expf(-gn0));
            float gt1 = gn1 / (1.f + __expf(-gn1));
            res[q] = __floats2half2_rn(vf.x * gt0, vf.y * gt1);
        }
        *(uint4*)&Bsm[r * VSTR + j * 8] = *(uint4*)res;
    }
    __syncthreads();

    const uint32_t AhU = smem_u32(Ah), BsU = smem_u32(Bsm);
    const int arow = lane & 15, achk = lane >> 4;
    const int gid = lane >> 2, tig = lane & 3;

    float acc[4][4][4];
    #pragma unroll
    for (int mi = 0; mi < 4; mi++)
        #pragma unroll
        for (int j = 0; j < 4; j++)
            #pragma unroll
            for (int q = 0; q < 4; q++) acc[mi][j][q] = 0.f;

    #pragma unroll
    for (int ks = 0; ks < 4; ks++) {
        uint32_t ra[4][4];
        #pragma unroll
        for (int mi = 0; mi < 4; mi++)
            ldsm4(ra[mi], AhU + (uint32_t)((mi * 16 + arow) * QSTR + ks * 16 + achk * 8) * 2u);
        uint32_t rb[2][4];
        #pragma unroll
        for (int nb = 0; nb < 2; nb++)
            ldsm4t(rb[nb], BsU + (uint32_t)((ks * 16 + arow) * VSTR + w * 32 + nb * 16 + achk * 8) * 2u);
        #pragma unroll
        for (int mi = 0; mi < 4; mi++)
            #pragma unroll
            for (int j = 0; j < 4; j++)
                mma_f16(acc[mi][j], ra[mi], &rb[j >> 1][(j & 1) * 2]);
    }

    #pragma unroll
    for (int mi = 0; mi < 4; mi++) {
        int row0 = mi * 16 + gid;
        #pragma unroll
        for (int j = 0; j < 4; j++) {
            int coln = w * 32 + j * 8 + 2 * tig;
            *(__half2*)(Ob + (size_t)row0 * NN + coln) =
                __floats2half2_rn(acc[mi][j][0], acc[mi][j][1]);
            *(__half2*)(Ob + (size_t)(row0 + 8) * NN + coln) =
                __floats2half2_rn(acc[mi][j][2], acc[mi][j][3]);
        }
    }
}

// ---------------- launch ----------------
extern "C" void kernel_launch(void* const* d_in, const int* in_sizes, int n_in,
                              void* d_out, int out_size)
{
    const float* x     = (const float*)d_in[0];
    const float* Wq    = (const float*)d_in[1];
    const float* Wk    = (const float*)d_in[2];
    const float* Wv    = (const float*)d_in[3];
    const float* dw_w  = (const float*)d_in[4];
    const float* gamma = (const float*)d_in[5];
    const float* beta  = (const float*)d_in[6];
    const float* temp  = (const float*)d_in[7];
    const float* Wp    = (const float*)d_in[8];
    const float* bp    = (const float*)d_in[9];
    float* out = (float*)d_out;

    __half *QKVh, *Gh, *Xh, *Wh, *Wph, *Oh, *Ah;
    cudaGetSymbolAddress((void**)&QKVh, g_QKVh);
    cudaGetSymbolAddress((void**)&Gh,   g_Gh);
    cudaGetSymbolAddress((void**)&Ah,   g_attnh);
    cudaGetSymbolAddress((void**)&Xh,   g_Xh);
    cudaGetSymbolAddress((void**)&Wh,   g_Wh);
    cudaGetSymbolAddress((void**)&Wph,  g_Wph);
    cudaGetSymbolAddress((void**)&Oh,   g_Oh);

    // lazy one-time creation (first call is outside graph capture)
    static bool s_init = false;
    static cudaStream_t s_side;
    static cudaEvent_t s_fork, s_join;
    if (!s_init) {
        cudaStreamCreateWithFlags(&s_side, cudaStreamNonBlocking);
        cudaEventCreateWithFlags(&s_fork, cudaEventDisableTiming);
        cudaEventCreateWithFlags(&s_join, cudaEventDisableTiming);
        cudaFuncSetAttribute(gemm_h<__half>, cudaFuncAttributeMaxDynamicSharedMemorySize, GEMM_SMEM);
        cudaFuncSetAttribute(gemm_h<float>,  cudaFuncAttributeMaxDynamicSharedMemorySize, GEMM_SMEM);
        s_init = true;
    }

    // ---- fork: gate branch (dwconv + BN stats) on side stream ----
    cudaEventRecord(s_fork, 0);
    cudaStreamWaitEvent(s_side, s_fork, 0);
    zero_bn_kernel<<<1, 512, 0, s_side>>>();
    dwconv_kernel<<<BB * CC, 256, 0, s_side>>>(x, dw_w, Gh);
    bn_finalize_kernel<<<1, 512, 0, s_side>>>(gamma, beta);
    cudaEventRecord(s_join, s_side);

    // ---- main stream: conversions -> QKV GEMM -> attention ----
    const int nW4all = 4 * CC * CC / 4;
    f2h_w_kernel<<<(nW4all + 255) / 256, 256>>>(Wq, Wk, Wv, Wp, Wh, Wph);
    const int nX4 = BB * CC * NN / 4;
    f2h_kernel<<<(nX4 + 255) / 256, 256>>>(x, Xh, nX4);

    gemm_h<__half><<<dim3(NN / 128, 3 * CC / TM, BB), 256, GEMM_SMEM>>>(Wh, Xh, QKVh, nullptr);

    attn_kernel<<<BB * HEADS, 128>>>(QKVh, QKVh + BCN, temp, Ah);

    // ---- join: attn_apply needs Gh + bnA/bnB ----
    cudaStreamWaitEvent(0, s_join, 0);
    attn_apply_kernel<<<dim3(BB * HEADS, NN / 128), 128>>>(Ah, QKVh + 2 * BCN, Gh, Oh);

    gemm_h<float><<<dim3(NN / 128, CC / TM, BB), 256, GEMM_SMEM>>>(Wph, Oh, (float*)out, bp);
}

// round 14
// speedup vs baseline: 1.0529x; 1.0529x over previous
#include <cuda_runtime.h>
#include <cuda_fp16.h>
#include <math.h>
#include <stdint.h>

#define BB 32
#define CC 512
#define NN 1024      // H*W = 32*32
#define HEADS 8
#define HD 64
#define BN_EPS 1e-5f
#define BCN ((size_t)BB * CC * NN)

// ---------------- scratch (device globals; no allocation allowed) ----------------
__device__ __half g_QKVh[3 * BCN];                // Q,K,V half
__device__ __half g_Gh[BCN];                      // dwconv output half
__device__ __half g_Oh[BCN];                      // attention output half
__device__ __half g_Xh[BCN];                      // x in half
__device__ __half g_Wh[3 * (size_t)CC * CC];      // Wq,Wk,Wv stacked half
__device__ __half g_Wph[(size_t)CC * CC];         // Wp half
__device__ __half g_attnh[(size_t)BB * HEADS * HD * HD];
__device__ float  g_bnsum[CC];
__device__ float  g_bnsum2[CC];
__device__ float  g_bnA[CC];
__device__ float  g_bnB[CC];

// ============================ helpers ============================
__device__ __forceinline__ uint32_t smem_u32(const void* p) {
    uint32_t a;
    asm("{ .reg .u64 t; cvta.to.shared.u64 t, %1; cvt.u32.u64 %0, t; }" : "=r"(a) : "l"(p));
    return a;
}
__device__ __forceinline__ void cp_async16(uint32_t dst, const void* src) {
    asm volatile("cp.async.cg.shared.global [%0], [%1], 16;" :: "r"(dst), "l"(src));
}
#define CP_COMMIT() asm volatile("cp.async.commit_group;" ::: "memory")
#define CP_WAIT(n)  asm volatile("cp.async.wait_group %0;" :: "n"(n) : "memory")

__device__ __forceinline__ void ldsm4(uint32_t* r, uint32_t addr) {
    asm volatile("ldmatrix.sync.aligned.m8n8.x4.shared.b16 {%0,%1,%2,%3}, [%4];"
        : "=r"(r[0]), "=r"(r[1]), "=r"(r[2]), "=r"(r[3]) : "r"(addr));
}
__device__ __forceinline__ void ldsm4t(uint32_t* r, uint32_t addr) {
    asm volatile("ldmatrix.sync.aligned.m8n8.x4.trans.shared.b16 {%0,%1,%2,%3}, [%4];"
        : "=r"(r[0]), "=r"(r[1]), "=r"(r[2]), "=r"(r[3]) : "r"(addr));
}
__device__ __forceinline__ void mma_f16(float* c, const uint32_t* a, const uint32_t* b) {
    asm volatile("mma.sync.aligned.m16n8k16.row.col.f32.f16.f16.f32 "
        "{%0,%1,%2,%3}, {%4,%5,%6,%7}, {%8,%9}, {%0,%1,%2,%3};"
        : "+f"(c[0]), "+f"(c[1]), "+f"(c[2]), "+f"(c[3])
        : "r"(a[0]), "r"(a[1]), "r"(a[2]), "r"(a[3]), "r"(b[0]), "r"(b[1]));
}

// ============================ small kernels ============================
__global__ void zero_bn_kernel() {
    int t = threadIdx.x;
    if (t < CC) { g_bnsum[t] = 0.f; g_bnsum2[t] = 0.f; }
}

__global__ void bn_finalize_kernel(const float* __restrict__ gamma,
                                   const float* __restrict__ beta) {
    int c = threadIdx.x;
    if (c < CC) {
        const float cnt = (float)(BB * NN);
        float mean = g_bnsum[c] / cnt;
        float var  = g_bnsum2[c] / cnt - mean * mean;
        float A = gamma[c] * rsqrtf(var + BN_EPS);
        g_bnA[c] = A;
        g_bnB[c] = beta[c] - mean * A;
    }
}

__global__ __launch_bounds__(256)
void f2h_kernel(const float* __restrict__ in, __half* __restrict__ out, int n4) {
    int i = blockIdx.x * 256 + threadIdx.x;
    if (i < n4) {
        float4 v = ((const float4*)in)[i];
        __half2* o = (__half2*)out;
        o[2 * i]     = __floats2half2_rn(v.x, v.y);
        o[2 * i + 1] = __floats2half2_rn(v.z, v.w);
    }
}

__global__ __launch_bounds__(256)
void f2h_w_kernel(const float* __restrict__ wq, const float* __restrict__ wk,
                  const float* __restrict__ wv, const float* __restrict__ wp,
                  __half* __restrict__ wh, __half* __restrict__ wph)
{
    const int n4 = CC * CC / 4;
    int i = blockIdx.x * 256 + threadIdx.x;
    int m = i / n4, r = i - m * n4;
    const float* src = (m == 0) ? wq : (m == 1) ? wk : (m == 2) ? wv : wp;
    __half* dst = (m < 3) ? (wh + (size_t)m * CC * CC) : wph;
    float4 v = ((const float4*)src)[r];
    __half2* o = (__half2*)dst;
    o[2 * r]     = __floats2half2_rn(v.x, v.y);
    o[2 * r + 1] = __floats2half2_rn(v.z, v.w);
}

// ---- fp16 tensor GEMM: CTA tile 128x128, warp tile 32x64, 4-stage cp.async (R8 config) ----
#define ASTRH 40
#define BSTRH 136
#define STAGES 4
#define A_STAGE_BYTES (128 * ASTRH * 2)           // 10240
#define B_STAGE_BYTES (32 * BSTRH * 2)            // 8704
#define STAGE_BYTES (A_STAGE_BYTES + B_STAGE_BYTES)   // 18944
#define GEMM_SMEM (STAGES * STAGE_BYTES)          // 75776

template <typename OT>
__global__ __launch_bounds__(256)
void gemm_h(const __half* __restrict__ A, const __half* __restrict__ Bh,
            OT* __restrict__ Y, const float* __restrict__ bias)
{
    extern __shared__ __half dsm[];
    const uint32_t base = smem_u32(dsm);

    const int t    = threadIdx.x;
    const int lane = t & 31;
    const int wid  = t >> 5;
    const int wm   = wid & 3;
    const int wn   = wid >> 2;
    const int m0g  = blockIdx.y * 128;
    const int mat  = m0g >> 9;
    const int mrow0 = m0g & 511;
    const int n0   = blockIdx.x * 128;
    const int b    = blockIdx.z;

    const __half* Ag = A + (size_t)m0g * CC;
    const __half* Bg = Bh + (size_t)b * CC * NN + n0;
    OT*           Yb = Y + (size_t)mat * BCN + (size_t)b * CC * NN;

    float acc[2][8][4];
    #pragma unroll
    for (int i = 0; i < 2; i++)
        #pragma unroll
        for (int j = 0; j < 8; j++)
            #pragma unroll
            for (int q = 0; q < 4; q++) acc[i][j][q] = 0.f;

    auto ld_stage = [&](int s, int k0) {
        const uint32_t au = base + (uint32_t)s * STAGE_BYTES;
        const uint32_t bu = au + A_STAGE_BYTES;
        #pragma unroll
        for (int i = 0; i < 2; i++) {
            int idx = t + 256 * i;
            int r = idx >> 2, j = idx & 3;
            cp_async16(au + (uint32_t)(r * ASTRH + j * 8) * 2u,
                       Ag + (size_t)r * CC + k0 + j * 8);
        }
        #pragma unroll
        for (int i = 0; i < 2; i++) {
            int idx = t + 256 * i;
            int r = idx >> 4, j = idx & 15;
            cp_async16(bu + (uint32_t)(r * BSTRH + j * 8) * 2u,
                       Bg + (size_t)(k0 + r) * NN + j * 8);
        }
    };

    #pragma unroll
    for (int s = 0; s < STAGES - 1; s++) { ld_stage(s, s * 32); CP_COMMIT(); }

    const int gid = lane >> 2, tig = lane & 3;
    const int arow = lane & 15, achk = lane >> 4;

    for (int c = 0; c < 16; c++) {
        CP_WAIT(STAGES - 2);
        __syncthreads();

        const uint32_t Au = base + (uint32_t)(c & (STAGES - 1)) * STAGE_BYTES;
        const uint32_t Bu = Au + A_STAGE_BYTES;

        #pragma unroll
        for (int ks = 0; ks < 2; ks++) {
            uint32_t ra[2][4];
            #pragma unroll
            for (int mi = 0; mi < 2; mi++) {
                int row = wm * 32 + mi * 16 + arow;
                ldsm4(ra[mi], Au + (uint32_t)(row * ASTRH + ks * 16 + achk * 8) * 2u);
            }
            uint32_t rb[4][4];
            #pragma unroll
            for (int nb = 0; nb < 4; nb++) {
                int krow = ks * 16 + arow;
                int col  = wn * 64 + nb * 16 + achk * 8;
                ldsm4t(rb[nb], Bu + (uint32_t)(krow * BSTRH + col) * 2u);
            }
            #pragma unroll
            for (int mi = 0; mi < 2; mi++)
                #pragma unroll
                for (int j = 0; j < 8; j++)
                    mma_f16(acc[mi][j], ra[mi], &rb[j >> 1][(j & 1) * 2]);
        }

        if (c + STAGES - 1 < 16) ld_stage((c + STAGES - 1) & (STAGES - 1),
                                          (c + STAGES - 1) * 32);
        CP_COMMIT();
    }

    #pragma unroll
    for (int i = 0; i < 2; i++) {
        int ml = mrow0 + wm * 32 + i * 16 + gid;
        float b0 = bias ? bias[ml] : 0.f;
        float b1 = bias ? bias[ml + 8] : 0.f;
        OT* r0 = Yb + (size_t)ml * NN + n0 + wn * 64;
        OT* r1 = r0 + 8 * NN;
        #pragma unroll
        for (int j = 0; j < 8; j++) {
            int cb = j * 8 + 2 * tig;
            if constexpr (sizeof(OT) == 4) {
                *(float2*)((float*)r0 + cb) = make_float2(acc[i][j][0] + b0, acc[i][j][1] + b0);
                *(float2*)((float*)r1 + cb) = make_float2(acc[i][j][2] + b1, acc[i][j][3] + b1);
            } else {
                *(__half2*)((__half*)r0 + cb) = __floats2half2_rn(acc[i][j][0] + b0, acc[i][j][1] + b0);
                *(__half2*)((__half*)r1 + cb) = __floats2half2_rn(acc[i][j][2] + b1, acc[i][j][3] + b1);
            }
        }
    }
}

// ---- attn = softmax( (Q K^T)/(|q||k|) * temp ) per (b,h), tensor-core gram, half out ----
#define QSTR 72
__global__ __launch_bounds__(128)
void attn_kernel(const __half* __restrict__ Q, const __half* __restrict__ K,
                 const float* __restrict__ temp, __half* __restrict__ attn)
{
    const int bh = blockIdx.x;
    const int b = bh / HEADS, h = bh % HEADS;
    const __half* Qb = Q + (size_t)b * CC * NN + (size_t)h * HD * NN;
    const __half* Kb = K + (size_t)b * CC * NN + (size_t)h * HD * NN;

    __shared__ __half Qs[64 * QSTR];
    __shared__ __half Ks[64 * QSTR];
    __shared__ float Ss[64 * 65];
    __shared__ float ssq[64], ssk[64], inv_q[64], inv_k[64];

    const int t = threadIdx.x;
    const int lane = t & 31;
    const int wid = t >> 5;
    const int wm = wid >> 1, wn = wid & 1;

    if (t < 64) { ssq[t] = 0.f; ssk[t] = 0.f; }
    __syncthreads();

    const uint32_t QsU = smem_u32(Qs), KsU = smem_u32(Ks);

    float acc[2][4][4];
    #pragma unroll
    for (int mi = 0; mi < 2; mi++)
        #pragma unroll
        for (int j = 0; j < 4; j++)
            #pragma unroll
            for (int q = 0; q < 4; q++) acc[mi][j][q] = 0.f;

    float accq4[4] = {0.f, 0.f, 0.f, 0.f};
    float acck4[4] = {0.f, 0.f, 0.f, 0.f};

    for (int ch = 0; ch < 16; ch++) {
        const int n0 = ch * 64;
        #pragma unroll
        for (int i = 0; i < 4; i++) {
            int c = t + 128 * i;
            int r = c >> 3, j = c & 7;
            uint4 v = *(const uint4*)(Qb + (size_t)r * NN + n0 + j * 8);
            *(uint4*)&Qs[r * QSTR + j * 8] = v;
            const __half2* hp = (const __half2*)&v;
            #pragma unroll
            for (int q = 0; q < 4; q++) { float2 f = __half22float2(hp[q]); accq4[i] += f.x * f.x + f.y * f.y; }
            uint4 w = *(const uint4*)(Kb + (size_t)r * NN + n0 + j * 8);
            *(uint4*)&Ks[r * QSTR + j * 8] = w;
            const __half2* hq = (const __half2*)&w;
            #pragma unroll
            for (int q = 0; q < 4; q++) { float2 f = __half22float2(hq[q]); acck4[i] += f.x * f.x + f.y * f.y; }
        }
        __syncthreads();

        #pragma unroll
        for (int ks = 0; ks < 4; ks++) {
            uint32_t ra[2][4], rb[2][4];
            #pragma unroll
            for (int mi = 0; mi < 2; mi++)
                ldsm4(ra[mi], QsU + (uint32_t)((wm * 32 + mi * 16 + (lane & 15)) * QSTR
                                               + ks * 16 + (lane >> 4) * 8) * 2u);
            #pragma unroll
            for (int nb = 0; nb < 2; nb++)
                ldsm4(rb[nb], KsU + (uint32_t)((wn * 32 + nb * 16 + (lane & 15)) * QSTR
                                               + ks * 16 + (lane >> 4) * 8) * 2u);
            #pragma unroll
            for (int mi = 0; mi < 2; mi++)
                #pragma unroll
                for (int j = 0; j < 4; j++) {
                    uint32_t bb[2] = { rb[j >> 1][j & 1], rb[j >> 1][(j & 1) + 2] };
                    mma_f16(acc[mi][j], ra[mi], bb);
                }
        }
        __syncthreads();
    }

    #pragma unroll
    for (int i = 0; i < 4; i++) {
        int r = (t + 128 * i) >> 3;
        atomicAdd(&ssq[r], accq4[i]);
        atomicAdd(&ssk[r], acck4[i]);
    }
    __syncthreads();

    if (t < 64) {
        inv_q[t] = 1.f / fmaxf(sqrtf(ssq[t]), 1e-12f);
        inv_k[t] = 1.f / fmaxf(sqrtf(ssk[t]), 1e-12f);
    }
    __syncthreads();

    const float tmp = temp[h];
    const int gid = lane >> 2, tig = lane & 3;
    #pragma unroll
    for (int mi = 0; mi < 2; mi++)
        #pragma unroll
        for (int j = 0; j < 4; j++)
            #pragma unroll
            for (int q = 0; q < 4; q++) {
                int m = wm * 32 + mi * 16 + gid + ((q >> 1) << 3);
                int n = wn * 32 + j * 8 + 2 * tig + (q & 1);
                Ss[m * 65 + n] = acc[mi][j][q] * inv_q[m] * inv_k[n] * tmp;
            }
    __syncthreads();

    if (t < 64) {
        float mx = -1e30f;
        #pragma unroll 8
        for (int e = 0; e < 64; e++) mx = fmaxf(mx, Ss[t * 65 + e]);
        float sum = 0.f;
        #pragma unroll 8
        for (int e = 0; e < 64; e++) {
            float ev = __expf(Ss[t * 65 + e] - mx);
            Ss[t * 65 + e] = ev; sum += ev;
        }
        float inv = 1.f / sum;
        __half* out = attn + ((size_t)bh * HD + t) * HD;
        #pragma unroll 8
        for (int e = 0; e < 64; e += 2)
            *(__half2*)(out + e) = __floats2half2_rn(Ss[t * 65 + e] * inv,
                                                     Ss[t * 65 + e + 1] * inv);
    }
}

// ---------------- depthwise 3x3 conv (half out) + per-channel stats ----------------
__global__ __launch_bounds__(256)
void dwconv_kernel(const float* __restrict__ x, const float* __restrict__ dw,
                   __half* __restrict__ g)
{
    const int bc = blockIdx.x;
    const int c = bc % CC;
    const float* img = x + (size_t)bc * NN;

    __shared__ float sm[34][34];
    const int t = threadIdx.x;
    for (int i = t; i < 34 * 34; i += 256) {
        int yy = i / 34 - 1, xx = i % 34 - 1;
        sm[i / 34][i % 34] =
            (yy >= 0 && yy < 32 && xx >= 0 && xx < 32) ? img[yy * 32 + xx] : 0.f;
    }
    float w[9];
    #pragma unroll
    for (int i = 0; i < 9; i++) w[i] = dw[c * 9 + i];
    __syncthreads();

    float s = 0.f, s2 = 0.f;
    for (int p = t; p < NN; p += 256) {
        int y = p >> 5, xx = p & 31;
        float acc = 0.f;
        #pragma unroll
        for (int dy = 0; dy < 3; dy++)
            #pragma unroll
            for (int dx = 0; dx < 3; dx++)
                acc += sm[y + dy][xx + dx] * w[dy * 3 + dx];
        g[(size_t)bc * NN + p] = __float2half_rn(acc);
        s += acc; s2 += acc * acc;
    }

    __shared__ float r1[256], r2[256];
    r1[t] = s; r2[t] = s2; __syncthreads();
    for (int st = 128; st > 0; st >>= 1) {
        if (t < st) { r1[t] += r1[t + st]; r2[t] += r2[t + st]; }
        __syncthreads();
    }
    if (t == 0) { atomicAdd(&g_bnsum[c], r1[0]); atomicAdd(&g_bnsum2[c], r2[0]); }
}

// ---- tensorized: O[b,h](64 x 128chunk) = attn(64x64,half) @ (V*silu(bn(G)))(64x128) ----
#define VSTR 136
__global__ __launch_bounds__(128)
void attn_apply_kernel(const __half* __restrict__ attn, const __half* __restrict__ v,
                       const __half* __restrict__ gbuf, __half* __restrict__ o)
{
    const int bh = blockIdx.x;
    const int nc = blockIdx.y;
    const int b = bh / HEADS, h = bh % HEADS;
    const __half* A  = attn + (size_t)bh * HD * HD;
    const __half* Vb = v    + (size_t)b * CC * NN + (size_t)h * HD * NN + nc * 128;
    const __half* Gb = gbuf + (size_t)b * CC * NN + (size_t)h * HD * NN + nc * 128;
    __half*       Ob = o    + (size_t)b * CC * NN + (size_t)h * HD * NN + nc * 128;

    __shared__ __half Ah[64 * QSTR];
    __shared__ __half Bsm[64 * VSTR];
    __shared__ float sc[64], sh[64];

    const int t = threadIdx.x;
    const int lane = t & 31;
    const int w = t >> 5;

    if (t < 64) {
        sc[t] = g_bnA[h * 64 + t];
        sh[t] = g_bnB[h * 64 + t];
    }
    #pragma unroll
    for (int i = 0; i < 4; i++) {
        int cidx = t + 128 * i;
        int r = cidx >> 3, j = cidx & 7;
        *(uint4*)&Ah[r * QSTR + j * 8] = *(const uint4*)(A + r * 64 + j * 8);
    }
    __syncthreads();

    #pragma unroll
    for (int i = 0; i < 8; i++) {
        int cidx = t + 128 * i;
        int r = cidx >> 4, j = cidx & 15;
        uint4 vv = *(const uint4*)(Vb + (size_t)r * NN + j * 8);
        uint4 gg = *(const uint4*)(Gb + (size_t)r * NN + j * 8);
        const float Ac = sc[r], Bc = sh[r];
        __half2 res[4];
        const __half2* vp = (const __half2*)&vv;
        const __half2* gp = (const __half2*)&gg;
        #pragma unroll
        for (int q = 0; q < 4; q++) {
            float2 gf = __half22float2(gp[q]);
            float2 vf = __half22float2(vp[q]);
            float gn0 = gf.x * Ac + Bc, gn1 = gf.y * Ac + Bc;
            float gt0 = gn0 / (1.f + __expf(-gn0));
            float gt1 = gn1 / (1.f + __expf(-gn1));
            res[q] = __floats2half2_rn(vf.x * gt0, vf.y * gt1);
        }
        *(uint4*)&Bsm[r * VSTR + j * 8] = *(uint4*)res;
    }
    __syncthreads();

    const uint32_t AhU = smem_u32(Ah), BsU = smem_u32(Bsm);
    const int arow = lane & 15, achk = lane >> 4;
    const int gid = lane >> 2, tig = lane & 3;

    float acc[4][4][4];
    #pragma unroll
    for (int mi = 0; mi < 4; mi++)
        #pragma unroll
        for (int j = 0; j < 4; j++)
            #pragma unroll
            for (int q = 0; q < 4; q++) acc[mi][j][q] = 0.f;

    #pragma unroll
    for (int ks = 0; ks < 4; ks++) {
        uint32_t ra[4][4];
        #pragma unroll
        for (int mi = 0; mi < 4; mi++)
            ldsm4(ra[mi], AhU + (uint32_t)((mi * 16 + arow) * QSTR + ks * 16 + achk * 8) * 2u);
        uint32_t rb[2][4];
        #pragma unroll
        for (int nb = 0; nb < 2; nb++)
            ldsm4t(rb[nb], BsU + (uint32_t)((ks * 16 + arow) * VSTR + w * 32 + nb * 16 + achk * 8) * 2u);
        #pragma unroll
        for (int mi = 0; mi < 4; mi++)
            #pragma unroll
            for (int j = 0; j < 4; j++)
                mma_f16(acc[mi][j], ra[mi], &rb[j >> 1][(j & 1) * 2]);
    }

    #pragma unroll
    for (int mi = 0; mi < 4; mi++) {
        int row0 = mi * 16 + gid;
        #pragma unroll
        for (int j = 0; j < 4; j++) {
            int coln = w * 32 + j * 8 + 2 * tig;
            *(__half2*)(Ob + (size_t)row0 * NN + coln) =
                __floats2half2_rn(acc[mi][j][0], acc[mi][j][1]);
            *(__half2*)(Ob + (size_t)(row0 + 8) * NN + coln) =
                __floats2half2_rn(acc[mi][j][2], acc[mi][j][3]);
        }
    }
}

// ---------------- launch ----------------
extern "C" void kernel_launch(void* const* d_in, const int* in_sizes, int n_in,
                              void* d_out, int out_size)
{
    const float* x     = (const float*)d_in[0];
    const float* Wq    = (const float*)d_in[1];
    const float* Wk    = (const float*)d_in[2];
    const float* Wv    = (const float*)d_in[3];
    const float* dw_w  = (const float*)d_in[4];
    const float* gamma = (const float*)d_in[5];
    const float* beta  = (const float*)d_in[6];
    const float* temp  = (const float*)d_in[7];
    const float* Wp    = (const float*)d_in[8];
    const float* bp    = (const float*)d_in[9];
    float* out = (float*)d_out;

    __half *QKVh, *Gh, *Xh, *Wh, *Wph, *Oh, *Ah;
    cudaGetSymbolAddress((void**)&QKVh, g_QKVh);
    cudaGetSymbolAddress((void**)&Gh,   g_Gh);
    cudaGetSymbolAddress((void**)&Ah,   g_attnh);
    cudaGetSymbolAddress((void**)&Xh,   g_Xh);
    cudaGetSymbolAddress((void**)&Wh,   g_Wh);
    cudaGetSymbolAddress((void**)&Wph,  g_Wph);
    cudaGetSymbolAddress((void**)&Oh,   g_Oh);

    // lazy one-time creation (first call is outside graph capture)
    static bool s_init = false;
    static cudaStream_t s_side;
    static cudaEvent_t s_fork, s_join;
    if (!s_init) {
        cudaStreamCreateWithFlags(&s_side, cudaStreamNonBlocking);
        cudaEventCreateWithFlags(&s_fork, cudaEventDisableTiming);
        cudaEventCreateWithFlags(&s_join, cudaEventDisableTiming);
        cudaFuncSetAttribute(gemm_h<__half>, cudaFuncAttributeMaxDynamicSharedMemorySize, GEMM_SMEM);
        cudaFuncSetAttribute(gemm_h<float>,  cudaFuncAttributeMaxDynamicSharedMemorySize, GEMM_SMEM);
        s_init = true;
    }

    // ---- fork: gate branch (dwconv + BN stats) on side stream ----
    cudaEventRecord(s_fork, 0);
    cudaStreamWaitEvent(s_side, s_fork, 0);
    zero_bn_kernel<<<1, 512, 0, s_side>>>();
    dwconv_kernel<<<BB * CC, 256, 0, s_side>>>(x, dw_w, Gh);
    bn_finalize_kernel<<<1, 512, 0, s_side>>>(gamma, beta);
    cudaEventRecord(s_join, s_side);

    // ---- main stream: conversions -> QKV GEMM -> attention ----
    const int nW4all = 4 * CC * CC / 4;
    f2h_w_kernel<<<(nW4all + 255) / 256, 256>>>(Wq, Wk, Wv, Wp, Wh, Wph);
    const int nX4 = BB * CC * NN / 4;
    f2h_kernel<<<(nX4 + 255) / 256, 256>>>(x, Xh, nX4);

    gemm_h<__half><<<dim3(NN / 128, 3 * CC / 128, BB), 256, GEMM_SMEM>>>(Wh, Xh, QKVh, nullptr);

    attn_kernel<<<BB * HEADS, 128>>>(QKVh, QKVh + BCN, temp, Ah);

    // ---- join: attn_apply needs Gh + bnA/bnB ----
    cudaStreamWaitEvent(0, s_join, 0);
    attn_apply_kernel<<<dim3(BB * HEADS, NN / 128), 128>>>(Ah, QKVh + 2 * BCN, Gh, Oh);

    gemm_h<float><<<dim3(NN / 128, CC / 128, BB), 256, GEMM_SMEM>>>(Wph, Oh, (float*)out, bp);
}

// round 16
// speedup vs baseline: 1.1083x; 1.0526x over previous
#include <cuda_runtime.h>
#include <cuda_fp16.h>
#include <math.h>
#include <stdint.h>

#define BB 32
#define CC 512
#define NN 1024      // H*W = 32*32
#define HEADS 8
#define HD 64
#define BN_EPS 1e-5f
#define BCN ((size_t)BB * CC * NN)

// ---------------- scratch (device globals; no allocation allowed) ----------------
__device__ __half g_QKVh[3 * BCN];                // Q,K,V half
__device__ __half g_Gh[BCN];                      // dwconv output half
__device__ __half g_Oh[BCN];                      // attention output half
__device__ __half g_Xh[BCN];                      // x in half
__device__ __half g_Wh[3 * (size_t)CC * CC];      // Wq,Wk,Wv stacked half
__device__ __half g_Wph[(size_t)CC * CC];         // Wp half
__device__ __half g_attnh[(size_t)BB * HEADS * HD * HD];
__device__ float  g_bnsum[CC];
__device__ float  g_bnsum2[CC];
__device__ float  g_bnA[CC];
__device__ float  g_bnB[CC];

// ============================ helpers ============================
__device__ __forceinline__ uint32_t smem_u32(const void* p) {
    uint32_t a;
    asm("{ .reg .u64 t; cvta.to.shared.u64 t, %1; cvt.u32.u64 %0, t; }" : "=r"(a) : "l"(p));
    return a;
}
__device__ __forceinline__ void cp_async16(uint32_t dst, const void* src) {
    asm volatile("cp.async.cg.shared.global [%0], [%1], 16;" :: "r"(dst), "l"(src));
}
#define CP_COMMIT() asm volatile("cp.async.commit_group;" ::: "memory")
#define CP_WAIT(n)  asm volatile("cp.async.wait_group %0;" :: "n"(n) : "memory")

__device__ __forceinline__ void ldsm4(uint32_t* r, uint32_t addr) {
    asm volatile("ldmatrix.sync.aligned.m8n8.x4.shared.b16 {%0,%1,%2,%3}, [%4];"
        : "=r"(r[0]), "=r"(r[1]), "=r"(r[2]), "=r"(r[3]) : "r"(addr));
}
__device__ __forceinline__ void ldsm4t(uint32_t* r, uint32_t addr) {
    asm volatile("ldmatrix.sync.aligned.m8n8.x4.trans.shared.b16 {%0,%1,%2,%3}, [%4];"
        : "=r"(r[0]), "=r"(r[1]), "=r"(r[2]), "=r"(r[3]) : "r"(addr));
}
__device__ __forceinline__ void mma_f16(float* c, const uint32_t* a, const uint32_t* b) {
    asm volatile("mma.sync.aligned.m16n8k16.row.col.f32.f16.f16.f32 "
        "{%0,%1,%2,%3}, {%4,%5,%6,%7}, {%8,%9}, {%0,%1,%2,%3};"
        : "+f"(c[0]), "+f"(c[1]), "+f"(c[2]), "+f"(c[3])
        : "r"(a[0]), "r"(a[1]), "r"(a[2]), "r"(a[3]), "r"(b[0]), "r"(b[1]));
}

// ============================ small kernels ============================
__global__ void zero_bn_kernel() {
    int t = threadIdx.x;
    if (t < CC) { g_bnsum[t] = 0.f; g_bnsum2[t] = 0.f; }
}

__global__ void bn_finalize_kernel(const float* __restrict__ gamma,
                                   const float* __restrict__ beta) {
    int c = threadIdx.x;
    if (c < CC) {
        const float cnt = (float)(BB * NN);
        float mean = g_bnsum[c] / cnt;
        float var  = g_bnsum2[c] / cnt - mean * mean;
        float A = gamma[c] * rsqrtf(var + BN_EPS);
        g_bnA[c] = A;
        g_bnB[c] = beta[c] - mean * A;
    }
}

__global__ __launch_bounds__(256)
void f2h_w_kernel(const float* __restrict__ wq, const float* __restrict__ wk,
                  const float* __restrict__ wv, const float* __restrict__ wp,
                  __half* __restrict__ wh, __half* __restrict__ wph)
{
    const int n4 = CC * CC / 4;
    int i = blockIdx.x * 256 + threadIdx.x;
    int m = i / n4, r = i - m * n4;
    const float* src = (m == 0) ? wq : (m == 1) ? wk : (m == 2) ? wv : wp;
    __half* dst = (m < 3) ? (wh + (size_t)m * CC * CC) : wph;
    float4 v = ((const float4*)src)[r];
    __half2* o = (__half2*)dst;
    o[2 * r]     = __floats2half2_rn(v.x, v.y);
    o[2 * r + 1] = __floats2half2_rn(v.z, v.w);
}

// ---- fp16 tensor GEMM: CTA tile 128x128, warp tile 32x64, BK=64, 2-stage ----
#define ASTRH 72
#define BSTRH 136
#define STAGES 2
#define A_STAGE_BYTES (128 * ASTRH * 2)           // 18432
#define B_STAGE_BYTES (64 * BSTRH * 2)            // 17408
#define STAGE_BYTES (A_STAGE_BYTES + B_STAGE_BYTES)   // 35840
#define GEMM_SMEM (STAGES * STAGE_BYTES)          // 71680

template <typename OT>
__global__ __launch_bounds__(256)
void gemm_h(const __half* __restrict__ A, const __half* __restrict__ Bh,
            OT* __restrict__ Y, const float* __restrict__ bias)
{
    extern __shared__ __half dsm[];
    const uint32_t base = smem_u32(dsm);

    const int t    = threadIdx.x;
    const int lane = t & 31;
    const int wid  = t >> 5;
    const int wm   = wid & 3;
    const int wn   = wid >> 2;
    const int m0g  = blockIdx.y * 128;
    const int mat  = m0g >> 9;
    const int mrow0 = m0g & 511;
    const int n0   = blockIdx.x * 128;
    const int b    = blockIdx.z;

    const __half* Ag = A + (size_t)m0g * CC;
    const __half* Bg = Bh + (size_t)b * CC * NN + n0;
    OT*           Yb = Y + (size_t)mat * BCN + (size_t)b * CC * NN;

    float acc[2][8][4];
    #pragma unroll
    for (int i = 0; i < 2; i++)
        #pragma unroll
        for (int j = 0; j < 8; j++)
            #pragma unroll
            for (int q = 0; q < 4; q++) acc[i][j][q] = 0.f;

    auto ld_stage = [&](int s, int k0) {
        const uint32_t au = base + (uint32_t)s * STAGE_BYTES;
        const uint32_t bu = au + A_STAGE_BYTES;
        #pragma unroll
        for (int i = 0; i < 4; i++) {              // A: 128x64 halves
            int idx = t + 256 * i;
            int r = idx >> 3, j = idx & 7;
            cp_async16(au + (uint32_t)(r * ASTRH + j * 8) * 2u,
                       Ag + (size_t)r * CC + k0 + j * 8);
        }
        #pragma unroll
        for (int i = 0; i < 4; i++) {              // B: 64x128 halves
            int idx = t + 256 * i;
            int r = idx >> 4, j = idx & 15;
            cp_async16(bu + (uint32_t)(r * BSTRH + j * 8) * 2u,
                       Bg + (size_t)(k0 + r) * NN + j * 8);
        }
    };

    ld_stage(0, 0);
    CP_COMMIT();

    const int gid = lane >> 2, tig = lane & 3;
    const int arow = lane & 15, achk = lane >> 4;

    for (int c = 0; c < 8; c++) {
        CP_WAIT(0);
        __syncthreads();

        if (c < 7) { ld_stage((c + 1) & 1, (c + 1) * 64); CP_COMMIT(); }

        const uint32_t Au = base + (uint32_t)(c & 1) * STAGE_BYTES;
        const uint32_t Bu = Au + A_STAGE_BYTES;

        #pragma unroll
        for (int ks = 0; ks < 4; ks++) {
            uint32_t ra[2][4];
            #pragma unroll
            for (int mi = 0; mi < 2; mi++) {
                int row = wm * 32 + mi * 16 + arow;
                ldsm4(ra[mi], Au + (uint32_t)(row * ASTRH + ks * 16 + achk * 8) * 2u);
            }
            uint32_t rb[4][4];
            #pragma unroll
            for (int nb = 0; nb < 4; nb++) {
                int krow = ks * 16 + arow;
                int col  = wn * 64 + nb * 16 + achk * 8;
                ldsm4t(rb[nb], Bu + (uint32_t)(krow * BSTRH + col) * 2u);
            }
            #pragma unroll
            for (int mi = 0; mi < 2; mi++)
                #pragma unroll
                for (int j = 0; j < 8; j++)
                    mma_f16(acc[mi][j], ra[mi], &rb[j >> 1][(j & 1) * 2]);
        }
        __syncthreads();
    }

    #pragma unroll
    for (int i = 0; i < 2; i++) {
        int ml = mrow0 + wm * 32 + i * 16 + gid;
        float b0 = bias ? bias[ml] : 0.f;
        float b1 = bias ? bias[ml + 8] : 0.f;
        OT* r0 = Yb + (size_t)ml * NN + n0 + wn * 64;
        OT* r1 = r0 + 8 * NN;
        #pragma unroll
        for (int j = 0; j < 8; j++) {
            int cb = j * 8 + 2 * tig;
            if constexpr (sizeof(OT) == 4) {
                *(float2*)((float*)r0 + cb) = make_float2(acc[i][j][0] + b0, acc[i][j][1] + b0);
                *(float2*)((float*)r1 + cb) = make_float2(acc[i][j][2] + b1, acc[i][j][3] + b1);
            } else {
                *(__half2*)((__half*)r0 + cb) = __floats2half2_rn(acc[i][j][0] + b0, acc[i][j][1] + b0);
                *(__half2*)((__half*)r1 + cb) = __floats2half2_rn(acc[i][j][2] + b1, acc[i][j][3] + b1);
            }
        }
    }
}

// ---- attn = softmax( (Q K^T)/(|q||k|) * temp ) per (b,h), tensor-core gram, half out ----
#define QSTR 72
__global__ __launch_bounds__(128)
void attn_kernel(const __half* __restrict__ Q, const __half* __restrict__ K,
                 const float* __restrict__ temp, __half* __restrict__ attn)
{
    const int bh = blockIdx.x;
    const int b = bh / HEADS, h = bh % HEADS;
    const __half* Qb = Q + (size_t)b * CC * NN + (size_t)h * HD * NN;
    const __half* Kb = K + (size_t)b * CC * NN + (size_t)h * HD * NN;

    __shared__ __half Qs[64 * QSTR];
    __shared__ __half Ks[64 * QSTR];
    __shared__ float Ss[64 * 65];
    __shared__ float ssq[64], ssk[64], inv_q[64], inv_k[64];

    const int t = threadIdx.x;
    const int lane = t & 31;
    const int wid = t >> 5;
    const int wm = wid >> 1, wn = wid & 1;

    if (t < 64) { ssq[t] = 0.f; ssk[t] = 0.f; }
    __syncthreads();

    const uint32_t QsU = smem_u32(Qs), KsU = smem_u32(Ks);

    float acc[2][4][4];
    #pragma unroll
    for (int mi = 0; mi < 2; mi++)
        #pragma unroll
        for (int j = 0; j < 4; j++)
            #pragma unroll
            for (int q = 0; q < 4; q++) acc[mi][j][q] = 0.f;

    float accq4[4] = {0.f, 0.f, 0.f, 0.f};
    float acck4[4] = {0.f, 0.f, 0.f, 0.f};

    for (int ch = 0; ch < 16; ch++) {
        const int n0 = ch * 64;
        #pragma unroll
        for (int i = 0; i < 4; i++) {
            int c = t + 128 * i;
            int r = c >> 3, j = c & 7;
            uint4 v = *(const uint4*)(Qb + (size_t)r * NN + n0 + j * 8);
            *(uint4*)&Qs[r * QSTR + j * 8] = v;
            const __half2* hp = (const __half2*)&v;
            #pragma unroll
            for (int q = 0; q < 4; q++) { float2 f = __half22float2(hp[q]); accq4[i] += f.x * f.x + f.y * f.y; }
            uint4 w = *(const uint4*)(Kb + (size_t)r * NN + n0 + j * 8);
            *(uint4*)&Ks[r * QSTR + j * 8] = w;
            const __half2* hq = (const __half2*)&w;
            #pragma unroll
            for (int q = 0; q < 4; q++) { float2 f = __half22float2(hq[q]); acck4[i] += f.x * f.x + f.y * f.y; }
        }
        __syncthreads();

        #pragma unroll
        for (int ks = 0; ks < 4; ks++) {
            uint32_t ra[2][4], rb[2][4];
            #pragma unroll
            for (int mi = 0; mi < 2; mi++)
                ldsm4(ra[mi], QsU + (uint32_t)((wm * 32 + mi * 16 + (lane & 15)) * QSTR
                                               + ks * 16 + (lane >> 4) * 8) * 2u);
            #pragma unroll
            for (int nb = 0; nb < 2; nb++)
                ldsm4(rb[nb], KsU + (uint32_t)((wn * 32 + nb * 16 + (lane & 15)) * QSTR
                                               + ks * 16 + (lane >> 4) * 8) * 2u);
            #pragma unroll
            for (int mi = 0; mi < 2; mi++)
                #pragma unroll
                for (int j = 0; j < 4; j++) {
                    uint32_t bb[2] = { rb[j >> 1][j & 1], rb[j >> 1][(j & 1) + 2] };
                    mma_f16(acc[mi][j], ra[mi], bb);
                }
        }
        __syncthreads();
    }

    #pragma unroll
    for (int i = 0; i < 4; i++) {
        int r = (t + 128 * i) >> 3;
        atomicAdd(&ssq[r], accq4[i]);
        atomicAdd(&ssk[r], acck4[i]);
    }
    __syncthreads();

    if (t < 64) {
        inv_q[t] = 1.f / fmaxf(sqrtf(ssq[t]), 1e-12f);
        inv_k[t] = 1.f / fmaxf(sqrtf(ssk[t]), 1e-12f);
    }
    __syncthreads();

    const float tmp = temp[h];
    const int gid = lane >> 2, tig = lane & 3;
    #pragma unroll
    for (int mi = 0; mi < 2; mi++)
        #pragma unroll
        for (int j = 0; j < 4; j++)
            #pragma unroll
            for (int q = 0; q < 4; q++) {
                int m = wm * 32 + mi * 16 + gid + ((q >> 1) << 3);
                int n = wn * 32 + j * 8 + 2 * tig + (q & 1);
                Ss[m * 65 + n] = acc[mi][j][q] * inv_q[m] * inv_k[n] * tmp;
            }
    __syncthreads();

    if (t < 64) {
        float mx = -1e30f;
        #pragma unroll 8
        for (int e = 0; e < 64; e++) mx = fmaxf(mx, Ss[t * 65 + e]);
        float sum = 0.f;
        #pragma unroll 8
        for (int e = 0; e < 64; e++) {
            float ev = __expf(Ss[t * 65 + e] - mx);
            Ss[t * 65 + e] = ev; sum += ev;
        }
        float inv = 1.f / sum;
        __half* out = attn + ((size_t)bh * HD + t) * HD;
        #pragma unroll 8
        for (int e = 0; e < 64; e += 2)
            *(__half2*)(out + e) = __floats2half2_rn(Ss[t * 65 + e] * inv,
                                                     Ss[t * 65 + e + 1] * inv);
    }
}

// ---------------- depthwise 3x3 conv (half out) + x->half + per-channel stats ----------------
__global__ __launch_bounds__(256)
void dwconv_kernel(const float* __restrict__ x, const float* __restrict__ dw,
                   __half* __restrict__ g, __half* __restrict__ xh)
{
    const int bc = blockIdx.x;
    const int c = bc % CC;
    const float* img = x + (size_t)bc * NN;

    __shared__ float sm[34][34];
    const int t = threadIdx.x;
    for (int i = t; i < 34 * 34; i += 256) {
        int yy = i / 34 - 1, xx = i % 34 - 1;
        sm[i / 34][i % 34] =
            (yy >= 0 && yy < 32 && xx >= 0 && xx < 32) ? img[yy * 32 + xx] : 0.f;
    }
    float w[9];
    #pragma unroll
    for (int i = 0; i < 9; i++) w[i] = dw[c * 9 + i];
    __syncthreads();

    float s = 0.f, s2 = 0.f;
    for (int p = t; p < NN; p += 256) {
        int y = p >> 5, xx = p & 31;
        float acc = 0.f;
        #pragma unroll
        for (int dy = 0; dy < 3; dy++)
            #pragma unroll
            for (int dx = 0; dx < 3; dx++)
                acc += sm[y + dy][xx + dx] * w[dy * 3 + dx];
        g[(size_t)bc * NN + p] = __float2half_rn(acc);
        xh[(size_t)bc * NN + p] = __float2half_rn(sm[y + 1][xx + 1]);
        s += acc; s2 += acc * acc;
    }

    __shared__ float r1[256], r2[256];
    r1[t] = s; r2[t] = s2; __syncthreads();
    for (int st = 128; st > 0; st >>= 1) {
        if (t < st) { r1[t] += r1[t + st]; r2[t] += r2[t + st]; }
        __syncthreads();
    }
    if (t == 0) { atomicAdd(&g_bnsum[c], r1[0]); atomicAdd(&g_bnsum2[c], r2[0]); }
}

// ---- tensorized: O[b,h](64 x 128chunk) = attn(64x64,half) @ (V*silu(bn(G)))(64x128) ----
#define VSTR 136
__global__ __launch_bounds__(128)
void attn_apply_kernel(const __half* __restrict__ attn, const __half* __restrict__ v,
                       const __half* __restrict__ gbuf, __half* __restrict__ o)
{
    const int bh = blockIdx.x;
    const int nc = blockIdx.y;
    const int b = bh / HEADS, h = bh % HEADS;
    const __half* A  = attn + (size_t)bh * HD * HD;
    const __half* Vb = v    + (size_t)b * CC * NN + (size_t)h * HD * NN + nc * 128;
    const __half* Gb = gbuf + (size_t)b * CC * NN + (size_t)h * HD * NN + nc * 128;
    __half*       Ob = o    + (size_t)b * CC * NN + (size_t)h * HD * NN + nc * 128;

    __shared__ __half Ah[64 * QSTR];
    __shared__ __half Bsm[64 * VSTR];
    __shared__ float sc[64], sh[64];

    const int t = threadIdx.x;
    const int lane = t & 31;
    const int w = t >> 5;

    if (t < 64) {
        sc[t] = g_bnA[h * 64 + t];
        sh[t] = g_bnB[h * 64 + t];
    }
    #pragma unroll
    for (int i = 0; i < 4; i++) {
        int cidx = t + 128 * i;
        int r = cidx >> 3, j = cidx & 7;
        *(uint4*)&Ah[r * QSTR + j * 8] = *(const uint4*)(A + r * 64 + j * 8);
    }
    __syncthreads();

    #pragma unroll
    for (int i = 0; i < 8; i++) {
        int cidx = t + 128 * i;
        int r = cidx >> 4, j = cidx & 15;
        uint4 vv = *(const uint4*)(Vb + (size_t)r * NN + j * 8);
        uint4 gg = *(const uint4*)(Gb + (size_t)r * NN + j * 8);
        const float Ac = sc[r], Bc = sh[r];
        __half2 res[4];
        const __half2* vp = (const __half2*)&vv;
        const __half2* gp = (const __half2*)&gg;
        #pragma unroll
        for (int q = 0; q < 4; q++) {
            float2 gf = __half22float2(gp[q]);
            float2 vf = __half22float2(vp[q]);
            float gn0 = gf.x * Ac + Bc, gn1 = gf.y * Ac + Bc;
            float gt0 = gn0 / (1.f + __expf(-gn0));
            float gt1 = gn1 / (1.f + __expf(-gn1));
            res[q] = __floats2half2_rn(vf.x * gt0, vf.y * gt1);
        }
        *(uint4*)&Bsm[r * VSTR + j * 8] = *(uint4*)res;
    }
    __syncthreads();

    const uint32_t AhU = smem_u32(Ah), BsU = smem_u32(Bsm);
    const int arow = lane & 15, achk = lane >> 4;
    const int gid = lane >> 2, tig = lane & 3;

    float acc[4][4][4];
    #pragma unroll
    for (int mi = 0; mi < 4; mi++)
        #pragma unroll
        for (int j = 0; j < 4; j++)
            #pragma unroll
            for (int q = 0; q < 4; q++) acc[mi][j][q] = 0.f;

    #pragma unroll
    for (int ks = 0; ks < 4; ks++) {
        uint32_t ra[4][4];
        #pragma unroll
        for (int mi = 0; mi < 4; mi++)
            ldsm4(ra[mi], AhU + (uint32_t)((mi * 16 + arow) * QSTR + ks * 16 + achk * 8) * 2u);
        uint32_t rb[2][4];
        #pragma unroll
        for (int nb = 0; nb < 2; nb++)
            ldsm4t(rb[nb], BsU + (uint32_t)((ks * 16 + arow) * VSTR + w * 32 + nb * 16 + achk * 8) * 2u);
        #pragma unroll
        for (int mi = 0; mi < 4; mi++)
            #pragma unroll
            for (int j = 0; j < 4; j++)
                mma_f16(acc[mi][j], ra[mi], &rb[j >> 1][(j & 1) * 2]);
    }

    #pragma unroll
    for (int mi = 0; mi < 4; mi++) {
        int row0 = mi * 16 + gid;
        #pragma unroll
        for (int j = 0; j < 4; j++) {
            int coln = w * 32 + j * 8 + 2 * tig;
            *(__half2*)(Ob + (size_t)row0 * NN + coln) =
                __floats2half2_rn(acc[mi][j][0], acc[mi][j][1]);
            *(__half2*)(Ob + (size_t)(row0 + 8) * NN + coln) =
                __floats2half2_rn(acc[mi][j][2], acc[mi][j][3]);
        }
    }
}

// ---------------- launch ----------------
extern "C" void kernel_launch(void* const* d_in, const int* in_sizes, int n_in,
                              void* d_out, int out_size)
{
    const float* x     = (const float*)d_in[0];
    const float* Wq    = (const float*)d_in[1];
    const float* Wk    = (const float*)d_in[2];
    const float* Wv    = (const float*)d_in[3];
    const float* dw_w  = (const float*)d_in[4];
    const float* gamma = (const float*)d_in[5];
    const float* beta  = (const float*)d_in[6];
    const float* temp  = (const float*)d_in[7];
    const float* Wp    = (const float*)d_in[8];
    const float* bp    = (const float*)d_in[9];
    float* out = (float*)d_out;

    __half *QKVh, *Gh, *Xh, *Wh, *Wph, *Oh, *Ah;
    cudaGetSymbolAddress((void**)&QKVh, g_QKVh);
    cudaGetSymbolAddress((void**)&Gh,   g_Gh);
    cudaGetSymbolAddress((void**)&Ah,   g_attnh);
    cudaGetSymbolAddress((void**)&Xh,   g_Xh);
    cudaGetSymbolAddress((void**)&Wh,   g_Wh);
    cudaGetSymbolAddress((void**)&Wph,  g_Wph);
    cudaGetSymbolAddress((void**)&Oh,   g_Oh);

    cudaFuncSetAttribute(gemm_h<__half>, cudaFuncAttributeMaxDynamicSharedMemorySize, GEMM_SMEM);
    cudaFuncSetAttribute(gemm_h<float>,  cudaFuncAttributeMaxDynamicSharedMemorySize, GEMM_SMEM);

    zero_bn_kernel<<<1, 512>>>();

    // dwconv: G (half), Xh (half), BN partial sums — single pass over x
    dwconv_kernel<<<BB * CC, 256>>>(x, dw_w, Gh, Xh);

    const int nW4all = 4 * CC * CC / 4;
    f2h_w_kernel<<<(nW4all + 255) / 256, 256>>>(Wq, Wk, Wv, Wp, Wh, Wph);

    // fused QKV GEMM: stacked A (1536x512), half output
    gemm_h<__half><<<dim3(NN / 128, 3 * CC / 128, BB), 256, GEMM_SMEM>>>(Wh, Xh, QKVh, nullptr);

    bn_finalize_kernel<<<1, 512>>>(gamma, beta);

    attn_kernel<<<BB * HEADS, 128>>>(QKVh, QKVh + BCN, temp, Ah);

    attn_apply_kernel<<<dim3(BB * HEADS, NN / 128), 128>>>(Ah, QKVh + 2 * BCN, Gh, Oh);

    gemm_h<float><<<dim3(NN / 128, CC / 128, BB), 256, GEMM_SMEM>>>(Wph, Oh, (float*)out, bp);
}